// round 11
// baseline (speedup 1.0000x reference)
#include <cuda_runtime.h>
#include <cuda_fp16.h>
#include <math.h>

constexpr int  B_ = 256, T_ = 512, I_ = 128, H_ = 256, L_ = 64, P_ = 50;
constexpr long BT = (long)B_ * T_;
constexpr long PMU_OFF = BT * I_, PLV_OFF = PMU_OFF + BT * L_;
constexpr long QMU_OFF = PLV_OFF + BT * L_, QLV_OFF = QMU_OFF + BT * L_;

__device__ float g_H[BT * H_];
__device__ float g_Z[BT * L_];
__device__ float g_preQM[BT * P_];
__device__ float g_preQL[BT * P_];
__device__ float g_preH[BT * P_];

using u64 = unsigned long long;
__device__ __forceinline__ u64 pk(float x, float y) {
    u64 r; asm("mov.b64 %0,{%1,%2};" : "=l"(r) : "f"(x), "f"(y)); return r;
}
__device__ __forceinline__ float2 up(u64 v) {
    float2 f; asm("mov.b64 {%0,%1},%2;" : "=f"(f.x), "=f"(f.y) : "l"(v)); return f;
}
__device__ __forceinline__ u64 f2fma(u64 a, u64 b, u64 c) {
    u64 d; asm("fma.rn.f32x2 %0,%1,%2,%3;" : "=l"(d) : "l"(a), "l"(b), "l"(c)); return d;
}
__device__ __forceinline__ float hsum(u64 v) { float2 f = up(v); return f.x + f.y; }
using ull2 = ulonglong2;

// ===================== Phase A: x pre-projections =====================
constexpr int ROWS_A = 64, XS = 132;
constexpr size_t SMEM_PRE = (size_t)(3 * P_ * XS + ROWS_A * XS + 3 * 64) * sizeof(float);

__global__ __launch_bounds__(256, 1) void k_pre(
    const float* __restrict__ x,
    const float* __restrict__ Wqm1, const float* __restrict__ bqm1,
    const float* __restrict__ Wql1, const float* __restrict__ bql1,
    const float* __restrict__ Wh1,  const float* __restrict__ bh1)
{
    extern __shared__ float sm[];
    float* sw = sm; float* sx = sw + 3 * P_ * XS; float* sb = sx + ROWS_A * XS;
    const int tid = threadIdx.x;
    const long bt0 = (long)blockIdx.x * ROWS_A;

    for (int idx = tid; idx < P_ * I_; idx += 256) {
        int j = idx >> 7, i = idx & 127;
        sw[j * XS + i] = Wqm1[j * 384 + i];
        sw[(P_ + j) * XS + i] = Wql1[j * 384 + i];
        sw[(2 * P_ + j) * XS + i] = Wh1[j * 448 + i];
    }
    for (int idx = tid; idx < ROWS_A * I_; idx += 256)
        sx[(idx >> 7) * XS + (idx & 127)] = x[bt0 * I_ + idx];
    if (tid < P_) { sb[tid] = bqm1[tid]; sb[64 + tid] = bql1[tid]; sb[128 + tid] = bh1[tid]; }
    __syncthreads();

    for (int task = tid; task < 480; task += 256) {
        int og = task >> 4, g = task & 15;
        const ull2* w4[5]; const ull2* x4[4];
        #pragma unroll
        for (int q = 0; q < 5; q++) w4[q] = (const ull2*)(sw + (og * 5 + q) * XS);
        #pragma unroll
        for (int rr = 0; rr < 4; rr++) x4[rr] = (const ull2*)(sx + (rr * 16 + g) * XS);
        u64 acc[5][4];
        #pragma unroll
        for (int q = 0; q < 5; q++)
            #pragma unroll
            for (int rr = 0; rr < 4; rr++) acc[q][rr] = 0;
        #pragma unroll 4
        for (int k = 0; k < I_ / 4; k++) {
            ull2 xv[4];
            #pragma unroll
            for (int rr = 0; rr < 4; rr++) xv[rr] = x4[rr][k];
            #pragma unroll
            for (int q = 0; q < 5; q++) {
                ull2 wv = w4[q][k];
                #pragma unroll
                for (int rr = 0; rr < 4; rr++) {
                    acc[q][rr] = f2fma(wv.x, xv[rr].x, acc[q][rr]);
                    acc[q][rr] = f2fma(wv.y, xv[rr].y, acc[q][rr]);
                }
            }
        }
        #pragma unroll
        for (int q = 0; q < 5; q++) {
            int o = og * 5 + q, m = o / P_, j = o - m * P_;
            float* dst = (m == 0) ? g_preQM : (m == 1) ? g_preQL : g_preH;
            float bias = sb[m * 64 + j];
            #pragma unroll
            for (int rr = 0; rr < 4; rr++)
                dst[(bt0 + rr * 16 + g) * P_ + j] = bias + hsum(acc[q][rr]);
        }
    }
}

// ===================== Phase B: sequential recurrence (512 threads) =====================
constexpr int WS = 260;
constexpr int O_W1 = 0, O_W2T = O_W1 + 3 * P_ * WS, O_B2 = O_W2T + 50 * 128;
constexpr int O_BH2 = O_B2 + 128, O_H = O_BH2 + 256, O_A1 = O_H + 4 * WS;
constexpr int O_VH = O_A1 + 200, O_AH = O_VH + 104, O_Z = O_AH + 104;
constexpr size_t SMEM_SEQ = (size_t)(O_Z + 136) * sizeof(float);

__global__ __launch_bounds__(512, 1) void k_seq(
    const float* __restrict__ hidden, const float* __restrict__ noise,
    const float* __restrict__ Wqm1, const float* __restrict__ Wqm2, const float* __restrict__ bqm2,
    const float* __restrict__ Wql1, const float* __restrict__ Wql2, const float* __restrict__ bql2,
    const float* __restrict__ Wh1,  const float* __restrict__ Wh2,  const float* __restrict__ bh2,
    float* __restrict__ out)
{
    extern __shared__ float sm[];
    float* sW1 = sm + O_W1; float* sW2t = sm + O_W2T; float* sb2 = sm + O_B2;
    float* sbh2 = sm + O_BH2; float* sH = sm + O_H; float* sA1 = sm + O_A1;
    float* sVH = sm + O_VH; float* sAH = sm + O_AH; float* sZ = sm + O_Z;

    const int tid = threadIdx.x;
    const int r0 = blockIdx.x * 2;

    for (int idx = tid; idx < P_ * H_; idx += 512) {
        int j = idx >> 8, k = idx & 255;
        sW1[j * WS + k] = Wqm1[j * 384 + 128 + k];
        sW1[(P_ + j) * WS + k] = Wql1[j * 384 + 128 + k];
        sW1[(2 * P_ + j) * WS + k] = Wh1[j * 448 + 128 + k];
    }
    for (int idx = tid; idx < L_ * P_; idx += 512) {
        int n = idx / P_, j = idx - n * P_;
        sW2t[j * 128 + 2 * n] = Wqm2[n * P_ + j];
        sW2t[j * 128 + 2 * n + 1] = Wql2[n * P_ + j];
    }
    if (tid < L_) { sb2[2 * tid] = bqm2[tid]; sb2[2 * tid + 1] = bql2[tid]; }
    if (tid < H_) sbh2[tid] = bh2[tid];
    for (int idx = tid; idx < 2 * H_; idx += 512)
        sH[(idx >> 8) * WS + (idx & 255)] = hidden[(r0 + (idx >> 8)) * H_ + (idx & 255)];
    if (tid == 0) { sAH[50] = sAH[51] = sAH[102] = sAH[103] = 0.f; }

    // s4 reg cache: thread (r=tid>>8, k=tid&255) holds Wh2[k][0..49] as 25 half2
    __half2 wh2s[25];
    float bh2c;
    {
        int k = tid & 255;
        #pragma unroll
        for (int i = 0; i < 25; i++)
            wh2s[i] = __floats2half2_rn(Wh2[k * P_ + 2 * i], Wh2[k * P_ + 2 * i + 1]);
        bh2c = bh2[k];
    }
    // s3 reg cache: tid<100 holds z-block of Wh1 row j = tid%50
    __half2 wzc[32];
    if (tid < 100) {
        int j = tid % 50;
        #pragma unroll
        for (int i = 0; i < 32; i++)
            wzc[i] = __floats2half2_rn(Wh1[j * 448 + 384 + 2 * i], Wh1[j * 448 + 384 + 2 * i + 1]);
    }
    __syncthreads();

    int cb = 0;
    for (int t = 0; t < T_; t++) {
        const long bt0 = (long)r0 * T_ + t, bt1 = bt0 + T_;
        float e = 0.f;
        if (tid < 128) e = noise[((tid >> 6) ? bt1 : bt0) * L_ + (tid & 63)];

        // ---- s1: 600 tasks (o,r,kh) half-K dots, shfl-combined; 16 warps busy ----
        for (int task = tid; task < 600; task += 512) {
            int o = task >> 2, r = (task >> 1) & 1, kh = task & 1;
            int m = o / 50, j = o - m * 50;
            unsigned mask = (task < 512) ? 0xFFFFFFFFu
                          : ((tid < 64) ? 0xFFFFFFFFu : 0x00FFFFFFu);
            long bt = r ? bt1 : bt0;
            float p = 0.f;
            if (kh == 0) {
                const float* pre = (m == 0) ? g_preQM : (m == 1) ? g_preQL : g_preH;
                p = pre[bt * P_ + j];
            }
            const ull2* w = (const ull2*)(sW1 + o * WS + kh * 128);
            const ull2* h = (const ull2*)(sH + (cb * 2 + r) * WS + kh * 128);
            u64 aA = 0, aB = 0;
            #pragma unroll 8
            for (int k2 = 0; k2 < 32; k2++) {
                ull2 wv = w[k2], hv = h[k2];
                aA = f2fma(wv.x, hv.x, aA);
                aB = f2fma(wv.y, hv.y, aB);
            }
            float s = hsum(aA) + hsum(aB);
            s += __shfl_xor_sync(mask, s, 1);
            if (kh == 0) {
                float v = p + s;
                if (m == 0)      sA1[j * 4 + 2 * r]     = fmaxf(v, 0.f);
                else if (m == 1) sA1[j * 4 + 2 * r + 1] = fmaxf(v, 0.f);
                else             sVH[r * 52 + j] = v;
            }
        }
        // h_t history stores (warps 14-15, overlapped with tail of s1)
        if (tid >= 448) {
            for (int idx = tid - 448; idx < 2 * H_; idx += 64) {
                int r = idx >> 8, k = idx & 255;
                g_H[(r ? bt1 : bt0) * H_ + k] = sH[(cb * 2 + r) * WS + k];
            }
        }
        __syncthreads();

        // ---- s2: 128 threads (r,n): packed (qmu,qlv), z ----
        if (tid < 128) {
            int r = tid >> 6, n = tid & 63;
            long bt = r ? bt1 : bt0;
            u64 acc = pk(sb2[2 * n], sb2[2 * n + 1]);
            const u64* wp = (const u64*)(sW2t + 2 * n);
            const u64* ap = (const u64*)(sA1 + 2 * r);
            #pragma unroll 10
            for (int j = 0; j < 50; j++)
                acc = f2fma(wp[j * 64], ap[j * 2], acc);
            float2 q = up(acc);
            out[QMU_OFF + bt * L_ + n] = q.x;
            out[QLV_OFF + bt * L_ + n] = q.y;
            float z = q.x + __expf(0.5f * q.y) * e;
            sZ[r * 68 + n] = z;
            g_Z[bt * L_ + n] = z;
        }
        __syncthreads();

        // ---- s3: add z-part (reg fp16 Wz), relu ----
        if (tid < 100) {
            int r = tid / 50, j = tid - r * 50;
            const float4* z4 = (const float4*)(sZ + r * 68);
            u64 acc1 = 0, acc2 = 0;
            #pragma unroll
            for (int i = 0; i < 16; i++) {
                float4 z = z4[i];
                float2 wa = __half22float2(wzc[2 * i]);
                float2 wb = __half22float2(wzc[2 * i + 1]);
                acc1 = f2fma(pk(wa.x, wa.y), pk(z.x, z.y), acc1);
                acc2 = f2fma(pk(wb.x, wb.y), pk(z.z, z.w), acc2);
            }
            sAH[r * 52 + j] = fmaxf(sVH[r * 52 + j] + hsum(acc1) + hsum(acc2), 0.f);
        }
        __syncthreads();

        // ---- s4: 512 threads, one h-output each (reg fp16 Wh2 row) ----
        {
            int r = tid >> 8, k = tid & 255;
            const u64* aa = (const u64*)(sAH + r * 52);
            u64 acc = 0, acc2 = 0;
            #pragma unroll
            for (int i = 0; i < 12; i += 2) {
                float2 w0 = __half22float2(wh2s[i]);
                acc  = f2fma(pk(w0.x, w0.y), aa[i], acc);
                float2 w1 = __half22float2(wh2s[i + 1]);
                acc2 = f2fma(pk(w1.x, w1.y), aa[i + 1], acc2);
            }
            #pragma unroll
            for (int i = 12; i < 25; i += 2) {
                float2 w0 = __half22float2(wh2s[i]);
                acc  = f2fma(pk(w0.x, w0.y), aa[i], acc);
                if (i + 1 < 25) {
                    float2 w1 = __half22float2(wh2s[i + 1]);
                    acc2 = f2fma(pk(w1.x, w1.y), aa[i + 1], acc2);
                }
            }
            int nb = cb ^ 1;
            sH[(nb * 2 + r) * WS + k] = bh2c + hsum(acc) + hsum(acc2);
        }
        __syncthreads();
        cb ^= 1;
    }
}

// ===================== Phase C1: p-branch MLPs =====================
constexpr int ROWS_P = 32;
constexpr int PO_W1 = 0, PO_W2 = PO_W1 + 2 * P_ * WS, PO_B1 = PO_W2 + 2 * L_ * P_;
constexpr int PO_B2 = PO_B1 + 128, PO_H = PO_B2 + 128, PO_A = PO_H + ROWS_P * WS;
constexpr size_t SMEM_P = (size_t)(PO_A + 2 * ROWS_P * 52) * sizeof(float);

__global__ __launch_bounds__(256, 1) void k_pbranch(
    const float* __restrict__ Wpm1, const float* __restrict__ bpm1,
    const float* __restrict__ Wpm2, const float* __restrict__ bpm2,
    const float* __restrict__ Wpl1, const float* __restrict__ bpl1,
    const float* __restrict__ Wpl2, const float* __restrict__ bpl2,
    float* __restrict__ out)
{
    extern __shared__ float sm[];
    float* sW1 = sm + PO_W1; float* sW2 = sm + PO_W2; float* sb1 = sm + PO_B1;
    float* sb2 = sm + PO_B2; float* sh = sm + PO_H; float* sa = sm + PO_A;
    const int tid = threadIdx.x;
    const long bt0 = (long)blockIdx.x * ROWS_P;

    for (int idx = tid; idx < P_ * H_; idx += 256) {
        int j = idx >> 8, k = idx & 255;
        sW1[j * WS + k] = Wpm1[idx];
        sW1[(P_ + j) * WS + k] = Wpl1[idx];
    }
    for (int idx = tid; idx < L_ * P_; idx += 256) {
        sW2[idx] = Wpm2[idx]; sW2[L_ * P_ + idx] = Wpl2[idx];
    }
    if (tid < P_) { sb1[tid] = bpm1[tid]; sb1[64 + tid] = bpl1[tid]; }
    if (tid < L_) { sb2[tid] = bpm2[tid]; sb2[64 + tid] = bpl2[tid]; }
    for (int idx = tid; idx < ROWS_P * H_; idx += 256)
        sh[(idx >> 8) * WS + (idx & 255)] = g_H[bt0 * H_ + idx];
    __syncthreads();

    if (tid < 100) {
        int op = tid >> 2, g = tid & 3;
        const ull2* w4[4]; const ull2* h4[8];
        #pragma unroll
        for (int q = 0; q < 4; q++) w4[q] = (const ull2*)(sW1 + (op * 4 + q) * WS);
        #pragma unroll
        for (int rr = 0; rr < 8; rr++) h4[rr] = (const ull2*)(sh + (rr * 4 + g) * WS);
        u64 acc[4][8];
        #pragma unroll
        for (int q = 0; q < 4; q++)
            #pragma unroll
            for (int rr = 0; rr < 8; rr++) acc[q][rr] = 0;
        #pragma unroll 4
        for (int k = 0; k < H_ / 4; k++) {
            ull2 hv[8];
            #pragma unroll
            for (int rr = 0; rr < 8; rr++) hv[rr] = h4[rr][k];
            #pragma unroll
            for (int q = 0; q < 4; q++) {
                ull2 wv = w4[q][k];
                #pragma unroll
                for (int rr = 0; rr < 8; rr++) {
                    acc[q][rr] = f2fma(wv.x, hv[rr].x, acc[q][rr]);
                    acc[q][rr] = f2fma(wv.y, hv[rr].y, acc[q][rr]);
                }
            }
        }
        #pragma unroll
        for (int q = 0; q < 4; q++) {
            int o = op * 4 + q, m = o / P_, j = o - m * P_;
            float bias = sb1[m * 64 + j];
            #pragma unroll
            for (int rr = 0; rr < 8; rr++)
                sa[(m * ROWS_P + rr * 4 + g) * 52 + j] = fmaxf(bias + hsum(acc[q][rr]), 0.f);
        }
    }
    __syncthreads();

    for (int task = tid; task < 2 * ROWS_P * L_; task += 256) {
        int m = task / (ROWS_P * L_); int rn = task - m * ROWS_P * L_;
        int r = rn >> 6, n = rn & 63;
        const float* w = sW2 + (m * L_ + n) * P_;
        const float* a = sa + (m * ROWS_P + r) * 52;
        float acc = sb2[m * 64 + n];
        #pragma unroll
        for (int j = 0; j < P_; j++) acc += w[j] * a[j];
        out[((m == 0) ? PMU_OFF : PLV_OFF) + (bt0 + r) * L_ + n] = acc;
    }
}

// ===================== Phase C2: x_hat =====================
constexpr int ROWS_O = 32, OS = 324;
constexpr int OO_W = 0, OO_H = OO_W + I_ * OS, OO_Z = OO_H + ROWS_O * WS;
constexpr int OO_B = OO_Z + ROWS_O * 68;
constexpr size_t SMEM_O = (size_t)(OO_B + 128) * sizeof(float);

__global__ __launch_bounds__(128, 1) void k_out(
    const float* __restrict__ Wo, const float* __restrict__ bo, float* __restrict__ out)
{
    extern __shared__ float sm[];
    float* sWo = sm + OO_W; float* sh = sm + OO_H; float* sz = sm + OO_Z; float* sbo = sm + OO_B;
    const int tid = threadIdx.x;
    const long bt0 = (long)blockIdx.x * ROWS_O;

    for (int idx = tid; idx < I_ * 320; idx += 128) {
        int i = idx / 320, c = idx - i * 320;
        sWo[i * OS + c] = Wo[idx];
    }
    for (int idx = tid; idx < ROWS_O * H_; idx += 128)
        sh[(idx >> 8) * WS + (idx & 255)] = g_H[bt0 * H_ + idx];
    for (int idx = tid; idx < ROWS_O * L_; idx += 128)
        sz[(idx >> 6) * 68 + (idx & 63)] = g_Z[bt0 * L_ + idx];
    if (tid < I_) sbo[tid] = bo[tid];
    __syncthreads();

    {
        int ig = tid >> 2, g = tid & 3;
        const ull2* w4[4]; const ull2* h4[8]; const ull2* z4[8];
        #pragma unroll
        for (int q = 0; q < 4; q++) w4[q] = (const ull2*)(sWo + (ig * 4 + q) * OS);
        #pragma unroll
        for (int rr = 0; rr < 8; rr++) {
            h4[rr] = (const ull2*)(sh + (rr * 4 + g) * WS);
            z4[rr] = (const ull2*)(sz + (rr * 4 + g) * 68);
        }
        u64 acc[4][8];
        #pragma unroll
        for (int q = 0; q < 4; q++)
            #pragma unroll
            for (int rr = 0; rr < 8; rr++) acc[q][rr] = 0;
        #pragma unroll 4
        for (int k = 0; k < H_ / 4; k++) {
            ull2 hv[8];
            #pragma unroll
            for (int rr = 0; rr < 8; rr++) hv[rr] = h4[rr][k];
            #pragma unroll
            for (int q = 0; q < 4; q++) {
                ull2 wv = w4[q][k];
                #pragma unroll
                for (int rr = 0; rr < 8; rr++) {
                    acc[q][rr] = f2fma(wv.x, hv[rr].x, acc[q][rr]);
                    acc[q][rr] = f2fma(wv.y, hv[rr].y, acc[q][rr]);
                }
            }
        }
        #pragma unroll
        for (int k = 0; k < L_ / 4; k++) {
            ull2 zv[8];
            #pragma unroll
            for (int rr = 0; rr < 8; rr++) zv[rr] = z4[rr][k];
            #pragma unroll
            for (int q = 0; q < 4; q++) {
                ull2 wv = w4[q][64 + k];
                #pragma unroll
                for (int rr = 0; rr < 8; rr++) {
                    acc[q][rr] = f2fma(wv.x, zv[rr].x, acc[q][rr]);
                    acc[q][rr] = f2fma(wv.y, zv[rr].y, acc[q][rr]);
                }
            }
        }
        #pragma unroll
        for (int q = 0; q < 4; q++) {
            int i = ig * 4 + q; float bias = sbo[i];
            #pragma unroll
            for (int rr = 0; rr < 8; rr++) {
                float v = bias + hsum(acc[q][rr]);
                out[(bt0 + rr * 4 + g) * I_ + i] = 1.0f / (1.0f + __expf(-v));
            }
        }
    }
}

// ===================== launch =====================
extern "C" void kernel_launch(void* const* d_in, const int* in_sizes, int n_in,
                              void* d_out, int out_size) {
    const float* x = (const float*)d_in[0];
    const float* hidden = (const float*)d_in[1];
    const float* noise = (const float*)d_in[2];
    const float* Wpm1 = (const float*)d_in[3];  const float* bpm1 = (const float*)d_in[4];
    const float* Wpm2 = (const float*)d_in[5];  const float* bpm2 = (const float*)d_in[6];
    const float* Wpl1 = (const float*)d_in[7];  const float* bpl1 = (const float*)d_in[8];
    const float* Wpl2 = (const float*)d_in[9];  const float* bpl2 = (const float*)d_in[10];
    const float* Wqm1 = (const float*)d_in[11]; const float* bqm1 = (const float*)d_in[12];
    const float* Wqm2 = (const float*)d_in[13]; const float* bqm2 = (const float*)d_in[14];
    const float* Wql1 = (const float*)d_in[15]; const float* bql1 = (const float*)d_in[16];
    const float* Wql2 = (const float*)d_in[17]; const float* bql2 = (const float*)d_in[18];
    const float* Wh1 = (const float*)d_in[19];  const float* bh1 = (const float*)d_in[20];
    const float* Wh2 = (const float*)d_in[21];  const float* bh2 = (const float*)d_in[22];
    const float* Wo = (const float*)d_in[23];   const float* bo = (const float*)d_in[24];
    float* out = (float*)d_out;

    cudaFuncSetAttribute(k_pre, cudaFuncAttributeMaxDynamicSharedMemorySize, (int)SMEM_PRE);
    cudaFuncSetAttribute(k_seq, cudaFuncAttributeMaxDynamicSharedMemorySize, (int)SMEM_SEQ);
    cudaFuncSetAttribute(k_pbranch, cudaFuncAttributeMaxDynamicSharedMemorySize, (int)SMEM_P);
    cudaFuncSetAttribute(k_out, cudaFuncAttributeMaxDynamicSharedMemorySize, (int)SMEM_O);

    k_pre<<<(int)(BT / ROWS_A), 256, SMEM_PRE>>>(x, Wqm1, bqm1, Wql1, bql1, Wh1, bh1);
    k_seq<<<B_ / 2, 512, SMEM_SEQ>>>(hidden, noise, Wqm1, Wqm2, bqm2,
                                     Wql1, Wql2, bql2, Wh1, Wh2, bh2, out);
    k_pbranch<<<(int)(BT / ROWS_P), 256, SMEM_P>>>(Wpm1, bpm1, Wpm2, bpm2,
                                                   Wpl1, bpl1, Wpl2, bpl2, out);
    k_out<<<(int)(BT / ROWS_O), 128, SMEM_O>>>(Wo, bo, out);
}

// round 12
// speedup vs baseline: 1.5205x; 1.5205x over previous
#include <cuda_runtime.h>
#include <cuda_fp16.h>
#include <math.h>

constexpr int  B_ = 256, T_ = 512, I_ = 128, H_ = 256, L_ = 64, P_ = 50;
constexpr long BT = (long)B_ * T_;
constexpr long PMU_OFF = BT * I_, PLV_OFF = PMU_OFF + BT * L_;
constexpr long QMU_OFF = PLV_OFF + BT * L_, QLV_OFF = QMU_OFF + BT * L_;

__device__ float g_H[BT * H_];
__device__ float g_Z[BT * L_];
__device__ float g_preQM[BT * P_];
__device__ float g_preQL[BT * P_];
__device__ float g_preH[BT * P_];

using u64 = unsigned long long;
__device__ __forceinline__ u64 pk(float x, float y) {
    u64 r; asm("mov.b64 %0,{%1,%2};" : "=l"(r) : "f"(x), "f"(y)); return r;
}
__device__ __forceinline__ float2 up(u64 v) {
    float2 f; asm("mov.b64 {%0,%1},%2;" : "=f"(f.x), "=f"(f.y) : "l"(v)); return f;
}
__device__ __forceinline__ u64 f2fma(u64 a, u64 b, u64 c) {
    u64 d; asm("fma.rn.f32x2 %0,%1,%2,%3;" : "=l"(d) : "l"(a), "l"(b), "l"(c)); return d;
}
__device__ __forceinline__ float hsum(u64 v) { float2 f = up(v); return f.x + f.y; }
using ull2 = ulonglong2;

// ===================== Phase A: x pre-projections =====================
constexpr int ROWS_A = 64, XS = 132;
constexpr size_t SMEM_PRE = (size_t)(3 * P_ * XS + ROWS_A * XS + 3 * 64) * sizeof(float);

__global__ __launch_bounds__(256, 1) void k_pre(
    const float* __restrict__ x,
    const float* __restrict__ Wqm1, const float* __restrict__ bqm1,
    const float* __restrict__ Wql1, const float* __restrict__ bql1,
    const float* __restrict__ Wh1,  const float* __restrict__ bh1)
{
    extern __shared__ float sm[];
    float* sw = sm; float* sx = sw + 3 * P_ * XS; float* sb = sx + ROWS_A * XS;
    const int tid = threadIdx.x;
    const long bt0 = (long)blockIdx.x * ROWS_A;

    for (int idx = tid; idx < P_ * I_; idx += 256) {
        int j = idx >> 7, i = idx & 127;
        sw[j * XS + i] = Wqm1[j * 384 + i];
        sw[(P_ + j) * XS + i] = Wql1[j * 384 + i];
        sw[(2 * P_ + j) * XS + i] = Wh1[j * 448 + i];
    }
    for (int idx = tid; idx < ROWS_A * I_; idx += 256)
        sx[(idx >> 7) * XS + (idx & 127)] = x[bt0 * I_ + idx];
    if (tid < P_) { sb[tid] = bqm1[tid]; sb[64 + tid] = bql1[tid]; sb[128 + tid] = bh1[tid]; }
    __syncthreads();

    for (int task = tid; task < 480; task += 256) {
        int og = task >> 4, g = task & 15;
        const ull2* w4[5]; const ull2* x4[4];
        #pragma unroll
        for (int q = 0; q < 5; q++) w4[q] = (const ull2*)(sw + (og * 5 + q) * XS);
        #pragma unroll
        for (int rr = 0; rr < 4; rr++) x4[rr] = (const ull2*)(sx + (rr * 16 + g) * XS);
        u64 acc[5][4];
        #pragma unroll
        for (int q = 0; q < 5; q++)
            #pragma unroll
            for (int rr = 0; rr < 4; rr++) acc[q][rr] = 0;
        #pragma unroll 4
        for (int k = 0; k < I_ / 4; k++) {
            ull2 xv[4];
            #pragma unroll
            for (int rr = 0; rr < 4; rr++) xv[rr] = x4[rr][k];
            #pragma unroll
            for (int q = 0; q < 5; q++) {
                ull2 wv = w4[q][k];
                #pragma unroll
                for (int rr = 0; rr < 4; rr++) {
                    acc[q][rr] = f2fma(wv.x, xv[rr].x, acc[q][rr]);
                    acc[q][rr] = f2fma(wv.y, xv[rr].y, acc[q][rr]);
                }
            }
        }
        #pragma unroll
        for (int q = 0; q < 5; q++) {
            int o = og * 5 + q, m = o / P_, j = o - m * P_;
            float* dst = (m == 0) ? g_preQM : (m == 1) ? g_preQL : g_preH;
            float bias = sb[m * 64 + j];
            #pragma unroll
            for (int rr = 0; rr < 4; rr++)
                dst[(bt0 + rr * 16 + g) * P_ + j] = bias + hsum(acc[q][rr]);
        }
    }
}

// ===================== Phase B: sequential recurrence (256 threads, R8 structure) =====================
constexpr int WS = 260;
constexpr int O_W1 = 0, O_W2T = O_W1 + 3 * P_ * WS, O_B2 = O_W2T + 50 * 128;
constexpr int O_BH2 = O_B2 + 128, O_H = O_BH2 + 256, O_A1 = O_H + 4 * WS;
constexpr int O_VH = O_A1 + 200, O_AH = O_VH + 104, O_Z = O_AH + 104;
constexpr size_t SMEM_SEQ = (size_t)(O_Z + 136) * sizeof(float);

__global__ __launch_bounds__(256, 1) void k_seq(
    const float* __restrict__ hidden, const float* __restrict__ noise,
    const float* __restrict__ Wqm1, const float* __restrict__ Wqm2, const float* __restrict__ bqm2,
    const float* __restrict__ Wql1, const float* __restrict__ Wql2, const float* __restrict__ bql2,
    const float* __restrict__ Wh1,  const float* __restrict__ Wh2,  const float* __restrict__ bh2,
    float* __restrict__ out)
{
    extern __shared__ float sm[];
    float* sW1 = sm + O_W1; float* sW2t = sm + O_W2T; float* sb2 = sm + O_B2;
    float* sbh2 = sm + O_BH2; float* sH = sm + O_H; float* sA1 = sm + O_A1;
    float* sVH = sm + O_VH; float* sAH = sm + O_AH; float* sZ = sm + O_Z;

    const int tid = threadIdx.x;
    const int r0 = blockIdx.x * 2;

    for (int idx = tid; idx < P_ * H_; idx += 256) {
        int j = idx >> 8, k = idx & 255;
        sW1[j * WS + k] = Wqm1[j * 384 + 128 + k];
        sW1[(P_ + j) * WS + k] = Wql1[j * 384 + 128 + k];
        sW1[(2 * P_ + j) * WS + k] = Wh1[j * 448 + 128 + k];
    }
    for (int idx = tid; idx < L_ * P_; idx += 256) {
        int n = idx / P_, j = idx - n * P_;
        sW2t[j * 128 + 2 * n] = Wqm2[n * P_ + j];
        sW2t[j * 128 + 2 * n + 1] = Wql2[n * P_ + j];
    }
    if (tid < L_) { sb2[2 * tid] = bqm2[tid]; sb2[2 * tid + 1] = bql2[tid]; }
    if (tid < H_) sbh2[tid] = bh2[tid];
    for (int idx = tid; idx < 2 * H_; idx += 256)
        sH[(idx >> 8) * WS + (idx & 255)] = hidden[(r0 + (idx >> 8)) * H_ + (idx & 255)];
    if (tid == 0) { sAH[50] = sAH[51] = sAH[102] = sAH[103] = 0.f; }

    __half2 wh2c[52];
    {
        int kp = tid & 127;
        #pragma unroll
        for (int j = 0; j < 50; j++)
            wh2c[j] = __floats2half2_rn(Wh2[2 * kp * P_ + j], Wh2[(2 * kp + 1) * P_ + j]);
        wh2c[50] = wh2c[51] = __floats2half2_rn(0.f, 0.f);
    }
    __half2 wzc[32];
    if (tid < 100) {
        int j = tid % 50;
        #pragma unroll
        for (int i = 0; i < 32; i++)
            wzc[i] = __floats2half2_rn(Wh1[j * 448 + 384 + 2 * i], Wh1[j * 448 + 384 + 2 * i + 1]);
    }
    __syncthreads();

    int cb = 0;
    for (int t = 0; t < T_; t++) {
        const long bt0 = (long)r0 * T_ + t, bt1 = bt0 + T_;
        float e0 = 0.f, e1 = 0.f;
        if (tid < 64) { e0 = noise[bt0 * L_ + tid]; e1 = noise[bt1 * L_ + tid]; }

        // s1: 100 threads (r,j), 3 full-K dots each; ull2 loads; 6 split acc chains
        if (tid < 100) {
            int r = tid & 1, j = tid >> 1;
            long bt = r ? bt1 : bt0;
            float p0 = g_preQM[bt * P_ + j];
            float p1 = g_preQL[bt * P_ + j];
            float p2 = g_preH[bt * P_ + j];
            const ull2* w0 = (const ull2*)(sW1 + j * WS);
            const ull2* w1 = (const ull2*)(sW1 + (P_ + j) * WS);
            const ull2* w2 = (const ull2*)(sW1 + (2 * P_ + j) * WS);
            const ull2* h4 = (const ull2*)(sH + (cb * 2 + r) * WS);
            u64 a0A = 0, a0B = 0, a1A = 0, a1B = 0, a2A = 0, a2B = 0;
            #pragma unroll 8
            for (int k = 0; k < 64; k++) {
                ull2 hv = h4[k];
                ull2 wv = w0[k];
                a0A = f2fma(wv.x, hv.x, a0A); a0B = f2fma(wv.y, hv.y, a0B);
                wv = w1[k];
                a1A = f2fma(wv.x, hv.x, a1A); a1B = f2fma(wv.y, hv.y, a1B);
                wv = w2[k];
                a2A = f2fma(wv.x, hv.x, a2A); a2B = f2fma(wv.y, hv.y, a2B);
            }
            float s0 = hsum(a0A) + hsum(a0B);
            float s1v = hsum(a1A) + hsum(a1B);
            float s2v = hsum(a2A) + hsum(a2B);
            sA1[j * 4 + 2 * r]     = fmaxf(p0 + s0, 0.f);
            sA1[j * 4 + 2 * r + 1] = fmaxf(p1 + s1v, 0.f);
            sVH[r * 52 + j] = p2 + s2v;
        } else {
            for (int idx = tid - 100; idx < 2 * H_; idx += 156) {
                int r = idx >> 8, k = idx & 255;
                g_H[(r ? bt1 : bt0) * H_ + k] = sH[(cb * 2 + r) * WS + k];
            }
        }
        __syncthreads();

        // s2: 64 threads, both rows, packed (qmu,qlv) + z
        if (tid < 64) {
            int n = tid;
            u64 accA = pk(sb2[2 * n], sb2[2 * n + 1]), accB = accA;
            const u64* wp = (const u64*)(sW2t + 2 * n);
            const ull2* ap = (const ull2*)sA1;
            #pragma unroll 10
            for (int j = 0; j < 50; j++) {
                u64 w = wp[j * 64];
                ull2 a = ap[j];
                accA = f2fma(w, a.x, accA);
                accB = f2fma(w, a.y, accB);
            }
            float2 q0 = up(accA), q1 = up(accB);
            out[QMU_OFF + bt0 * L_ + n] = q0.x; out[QLV_OFF + bt0 * L_ + n] = q0.y;
            out[QMU_OFF + bt1 * L_ + n] = q1.x; out[QLV_OFF + bt1 * L_ + n] = q1.y;
            float z0 = q0.x + __expf(0.5f * q0.y) * e0;
            float z1 = q1.x + __expf(0.5f * q1.y) * e1;
            sZ[n] = z0; sZ[68 + n] = z1;
            g_Z[bt0 * L_ + n] = z0; g_Z[bt1 * L_ + n] = z1;
        }
        __syncthreads();

        // s3: add z-part (reg fp16 Wz), relu
        if (tid < 100) {
            int r = tid / 50, j = tid - r * 50;
            const float4* z4 = (const float4*)(sZ + r * 68);
            u64 acc1 = 0, acc2 = 0;
            #pragma unroll
            for (int i = 0; i < 16; i++) {
                float4 z = z4[i];
                float2 wa = __half22float2(wzc[2 * i]);
                float2 wb = __half22float2(wzc[2 * i + 1]);
                acc1 = f2fma(pk(wa.x, wa.y), pk(z.x, z.y), acc1);
                acc2 = f2fma(pk(wb.x, wb.y), pk(z.z, z.w), acc2);
            }
            sAH[r * 52 + j] = fmaxf(sVH[r * 52 + j] + hsum(acc1) + hsum(acc2), 0.f);
        }
        __syncthreads();

        // s4: h_next = Wh2 @ a + bh2 (reg fp16 Wh2)
        {
            int r = tid >> 7, kp = tid & 127;
            const float4* a4 = (const float4*)(sAH + r * 52);
            float2 bb = *(const float2*)(sbh2 + 2 * kp);
            u64 acc = pk(bb.x, bb.y), acc2 = 0;
            #pragma unroll
            for (int q = 0; q < 13; q++) {
                float4 av = a4[q];
                float2 w0 = __half22float2(wh2c[4 * q]);     acc  = f2fma(pk(w0.x, w0.y), pk(av.x, av.x), acc);
                float2 w1 = __half22float2(wh2c[4 * q + 1]); acc2 = f2fma(pk(w1.x, w1.y), pk(av.y, av.y), acc2);
                float2 w2 = __half22float2(wh2c[4 * q + 2]); acc  = f2fma(pk(w2.x, w2.y), pk(av.z, av.z), acc);
                float2 w3 = __half22float2(wh2c[4 * q + 3]); acc2 = f2fma(pk(w3.x, w3.y), pk(av.w, av.w), acc2);
            }
            float2 r1 = up(acc), r2 = up(acc2);
            int nb = cb ^ 1;
            *(float2*)(sH + (nb * 2 + r) * WS + 2 * kp) = make_float2(r1.x + r2.x, r1.y + r2.y);
        }
        __syncthreads();
        cb ^= 1;
    }
}

// ===================== Phase C1: p-branch MLPs =====================
constexpr int ROWS_P = 32;
constexpr int PO_W1 = 0, PO_W2 = PO_W1 + 2 * P_ * WS, PO_B1 = PO_W2 + 2 * L_ * P_;
constexpr int PO_B2 = PO_B1 + 128, PO_H = PO_B2 + 128, PO_A = PO_H + ROWS_P * WS;
constexpr size_t SMEM_P = (size_t)(PO_A + 2 * ROWS_P * 52) * sizeof(float);

__global__ __launch_bounds__(256, 1) void k_pbranch(
    const float* __restrict__ Wpm1, const float* __restrict__ bpm1,
    const float* __restrict__ Wpm2, const float* __restrict__ bpm2,
    const float* __restrict__ Wpl1, const float* __restrict__ bpl1,
    const float* __restrict__ Wpl2, const float* __restrict__ bpl2,
    float* __restrict__ out)
{
    extern __shared__ float sm[];
    float* sW1 = sm + PO_W1; float* sW2 = sm + PO_W2; float* sb1 = sm + PO_B1;
    float* sb2 = sm + PO_B2; float* sh = sm + PO_H; float* sa = sm + PO_A;
    const int tid = threadIdx.x;
    const long bt0 = (long)blockIdx.x * ROWS_P;

    for (int idx = tid; idx < P_ * H_; idx += 256) {
        int j = idx >> 8, k = idx & 255;
        sW1[j * WS + k] = Wpm1[idx];
        sW1[(P_ + j) * WS + k] = Wpl1[idx];
    }
    for (int idx = tid; idx < L_ * P_; idx += 256) {
        sW2[idx] = Wpm2[idx]; sW2[L_ * P_ + idx] = Wpl2[idx];
    }
    if (tid < P_) { sb1[tid] = bpm1[tid]; sb1[64 + tid] = bpl1[tid]; }
    if (tid < L_) { sb2[tid] = bpm2[tid]; sb2[64 + tid] = bpl2[tid]; }
    for (int idx = tid; idx < ROWS_P * H_; idx += 256)
        sh[(idx >> 8) * WS + (idx & 255)] = g_H[bt0 * H_ + idx];
    __syncthreads();

    if (tid < 100) {
        int op = tid >> 2, g = tid & 3;
        const ull2* w4[4]; const ull2* h4[8];
        #pragma unroll
        for (int q = 0; q < 4; q++) w4[q] = (const ull2*)(sW1 + (op * 4 + q) * WS);
        #pragma unroll
        for (int rr = 0; rr < 8; rr++) h4[rr] = (const ull2*)(sh + (rr * 4 + g) * WS);
        u64 acc[4][8];
        #pragma unroll
        for (int q = 0; q < 4; q++)
            #pragma unroll
            for (int rr = 0; rr < 8; rr++) acc[q][rr] = 0;
        #pragma unroll 4
        for (int k = 0; k < H_ / 4; k++) {
            ull2 hv[8];
            #pragma unroll
            for (int rr = 0; rr < 8; rr++) hv[rr] = h4[rr][k];
            #pragma unroll
            for (int q = 0; q < 4; q++) {
                ull2 wv = w4[q][k];
                #pragma unroll
                for (int rr = 0; rr < 8; rr++) {
                    acc[q][rr] = f2fma(wv.x, hv[rr].x, acc[q][rr]);
                    acc[q][rr] = f2fma(wv.y, hv[rr].y, acc[q][rr]);
                }
            }
        }
        #pragma unroll
        for (int q = 0; q < 4; q++) {
            int o = op * 4 + q, m = o / P_, j = o - m * P_;
            float bias = sb1[m * 64 + j];
            #pragma unroll
            for (int rr = 0; rr < 8; rr++)
                sa[(m * ROWS_P + rr * 4 + g) * 52 + j] = fmaxf(bias + hsum(acc[q][rr]), 0.f);
        }
    }
    __syncthreads();

    for (int task = tid; task < 2 * ROWS_P * L_; task += 256) {
        int m = task / (ROWS_P * L_); int rn = task - m * ROWS_P * L_;
        int r = rn >> 6, n = rn & 63;
        const float* w = sW2 + (m * L_ + n) * P_;
        const float* a = sa + (m * ROWS_P + r) * 52;
        float acc = sb2[m * 64 + n];
        #pragma unroll
        for (int j = 0; j < P_; j++) acc += w[j] * a[j];
        out[((m == 0) ? PMU_OFF : PLV_OFF) + (bt0 + r) * L_ + n] = acc;
    }
}

// ===================== Phase C2: x_hat =====================
constexpr int ROWS_O = 32, OS = 324;
constexpr int OO_W = 0, OO_H = OO_W + I_ * OS, OO_Z = OO_H + ROWS_O * WS;
constexpr int OO_B = OO_Z + ROWS_O * 68;
constexpr size_t SMEM_O = (size_t)(OO_B + 128) * sizeof(float);

__global__ __launch_bounds__(128, 1) void k_out(
    const float* __restrict__ Wo, const float* __restrict__ bo, float* __restrict__ out)
{
    extern __shared__ float sm[];
    float* sWo = sm + OO_W; float* sh = sm + OO_H; float* sz = sm + OO_Z; float* sbo = sm + OO_B;
    const int tid = threadIdx.x;
    const long bt0 = (long)blockIdx.x * ROWS_O;

    for (int idx = tid; idx < I_ * 320; idx += 128) {
        int i = idx / 320, c = idx - i * 320;
        sWo[i * OS + c] = Wo[idx];
    }
    for (int idx = tid; idx < ROWS_O * H_; idx += 128)
        sh[(idx >> 8) * WS + (idx & 255)] = g_H[bt0 * H_ + idx];
    for (int idx = tid; idx < ROWS_O * L_; idx += 128)
        sz[(idx >> 6) * 68 + (idx & 63)] = g_Z[bt0 * L_ + idx];
    if (tid < I_) sbo[tid] = bo[tid];
    __syncthreads();

    {
        int ig = tid >> 2, g = tid & 3;
        const ull2* w4[4]; const ull2* h4[8]; const ull2* z4[8];
        #pragma unroll
        for (int q = 0; q < 4; q++) w4[q] = (const ull2*)(sWo + (ig * 4 + q) * OS);
        #pragma unroll
        for (int rr = 0; rr < 8; rr++) {
            h4[rr] = (const ull2*)(sh + (rr * 4 + g) * WS);
            z4[rr] = (const ull2*)(sz + (rr * 4 + g) * 68);
        }
        u64 acc[4][8];
        #pragma unroll
        for (int q = 0; q < 4; q++)
            #pragma unroll
            for (int rr = 0; rr < 8; rr++) acc[q][rr] = 0;
        #pragma unroll 4
        for (int k = 0; k < H_ / 4; k++) {
            ull2 hv[8];
            #pragma unroll
            for (int rr = 0; rr < 8; rr++) hv[rr] = h4[rr][k];
            #pragma unroll
            for (int q = 0; q < 4; q++) {
                ull2 wv = w4[q][k];
                #pragma unroll
                for (int rr = 0; rr < 8; rr++) {
                    acc[q][rr] = f2fma(wv.x, hv[rr].x, acc[q][rr]);
                    acc[q][rr] = f2fma(wv.y, hv[rr].y, acc[q][rr]);
                }
            }
        }
        #pragma unroll
        for (int k = 0; k < L_ / 4; k++) {
            ull2 zv[8];
            #pragma unroll
            for (int rr = 0; rr < 8; rr++) zv[rr] = z4[rr][k];
            #pragma unroll
            for (int q = 0; q < 4; q++) {
                ull2 wv = w4[q][64 + k];
                #pragma unroll
                for (int rr = 0; rr < 8; rr++) {
                    acc[q][rr] = f2fma(wv.x, zv[rr].x, acc[q][rr]);
                    acc[q][rr] = f2fma(wv.y, zv[rr].y, acc[q][rr]);
                }
            }
        }
        #pragma unroll
        for (int q = 0; q < 4; q++) {
            int i = ig * 4 + q; float bias = sbo[i];
            #pragma unroll
            for (int rr = 0; rr < 8; rr++) {
                float v = bias + hsum(acc[q][rr]);
                out[(bt0 + rr * 4 + g) * I_ + i] = 1.0f / (1.0f + __expf(-v));
            }
        }
    }
}

// ===================== launch =====================
extern "C" void kernel_launch(void* const* d_in, const int* in_sizes, int n_in,
                              void* d_out, int out_size) {
    const float* x = (const float*)d_in[0];
    const float* hidden = (const float*)d_in[1];
    const float* noise = (const float*)d_in[2];
    const float* Wpm1 = (const float*)d_in[3];  const float* bpm1 = (const float*)d_in[4];
    const float* Wpm2 = (const float*)d_in[5];  const float* bpm2 = (const float*)d_in[6];
    const float* Wpl1 = (const float*)d_in[7];  const float* bpl1 = (const float*)d_in[8];
    const float* Wpl2 = (const float*)d_in[9];  const float* bpl2 = (const float*)d_in[10];
    const float* Wqm1 = (const float*)d_in[11]; const float* bqm1 = (const float*)d_in[12];
    const float* Wqm2 = (const float*)d_in[13]; const float* bqm2 = (const float*)d_in[14];
    const float* Wql1 = (const float*)d_in[15]; const float* bql1 = (const float*)d_in[16];
    const float* Wql2 = (const float*)d_in[17]; const float* bql2 = (const float*)d_in[18];
    const float* Wh1 = (const float*)d_in[19];  const float* bh1 = (const float*)d_in[20];
    const float* Wh2 = (const float*)d_in[21];  const float* bh2 = (const float*)d_in[22];
    const float* Wo = (const float*)d_in[23];   const float* bo = (const float*)d_in[24];
    float* out = (float*)d_out;

    cudaFuncSetAttribute(k_pre, cudaFuncAttributeMaxDynamicSharedMemorySize, (int)SMEM_PRE);
    cudaFuncSetAttribute(k_seq, cudaFuncAttributeMaxDynamicSharedMemorySize, (int)SMEM_SEQ);
    cudaFuncSetAttribute(k_pbranch, cudaFuncAttributeMaxDynamicSharedMemorySize, (int)SMEM_P);
    cudaFuncSetAttribute(k_out, cudaFuncAttributeMaxDynamicSharedMemorySize, (int)SMEM_O);

    k_pre<<<(int)(BT / ROWS_A), 256, SMEM_PRE>>>(x, Wqm1, bqm1, Wql1, bql1, Wh1, bh1);
    k_seq<<<B_ / 2, 256, SMEM_SEQ>>>(hidden, noise, Wqm1, Wqm2, bqm2,
                                     Wql1, Wql2, bql2, Wh1, Wh2, bh2, out);
    k_pbranch<<<(int)(BT / ROWS_P), 256, SMEM_P>>>(Wpm1, bpm1, Wpm2, bpm2,
                                                   Wpl1, bpl1, Wpl2, bpl2, out);
    k_out<<<(int)(BT / ROWS_O), 128, SMEM_O>>>(Wo, bo, out);
}

// round 13
// speedup vs baseline: 1.5676x; 1.0309x over previous
#include <cuda_runtime.h>
#include <cuda_fp16.h>
#include <math.h>

constexpr int  B_ = 256, T_ = 512, I_ = 128, H_ = 256, L_ = 64, P_ = 50;
constexpr long BT = (long)B_ * T_;
constexpr long PMU_OFF = BT * I_, PLV_OFF = PMU_OFF + BT * L_;
constexpr long QMU_OFF = PLV_OFF + BT * L_, QLV_OFF = QMU_OFF + BT * L_;

__device__ float g_H[BT * H_];
__device__ float g_Z[BT * L_];
__device__ float g_preQM[BT * P_];
__device__ float g_preQL[BT * P_];
__device__ float g_preH[BT * P_];

using u64 = unsigned long long;
__device__ __forceinline__ u64 pk(float x, float y) {
    u64 r; asm("mov.b64 %0,{%1,%2};" : "=l"(r) : "f"(x), "f"(y)); return r;
}
__device__ __forceinline__ float2 up(u64 v) {
    float2 f; asm("mov.b64 {%0,%1},%2;" : "=f"(f.x), "=f"(f.y) : "l"(v)); return f;
}
__device__ __forceinline__ u64 f2fma(u64 a, u64 b, u64 c) {
    u64 d; asm("fma.rn.f32x2 %0,%1,%2,%3;" : "=l"(d) : "l"(a), "l"(b), "l"(c)); return d;
}
__device__ __forceinline__ float hsum(u64 v) { float2 f = up(v); return f.x + f.y; }
using ull2 = ulonglong2;

// ===================== Phase A: x pre-projections (weights from gmem) =====================
constexpr int ROWS_A = 64, XS = 132;
constexpr size_t SMEM_PRE = (size_t)(ROWS_A * XS + 192) * sizeof(float);

__global__ __launch_bounds__(256) void k_pre(
    const float* __restrict__ x,
    const float* __restrict__ Wqm1, const float* __restrict__ bqm1,
    const float* __restrict__ Wql1, const float* __restrict__ bql1,
    const float* __restrict__ Wh1,  const float* __restrict__ bh1)
{
    extern __shared__ float sm[];
    float* sx = sm; float* sb = sx + ROWS_A * XS;
    const int tid = threadIdx.x;
    const long bt0 = (long)blockIdx.x * ROWS_A;

    for (int idx = tid; idx < ROWS_A * I_; idx += 256)
        sx[(idx >> 7) * XS + (idx & 127)] = x[bt0 * I_ + idx];
    if (tid < P_) { sb[tid] = bqm1[tid]; sb[64 + tid] = bql1[tid]; sb[128 + tid] = bh1[tid]; }
    __syncthreads();

    for (int task = tid; task < 480; task += 256) {
        int og = task >> 4, g = task & 15;
        const ull2* w4[5]; int ms[5], js[5];
        #pragma unroll
        for (int q = 0; q < 5; q++) {
            int o = og * 5 + q, m = o / P_, j = o - m * P_;
            ms[q] = m; js[q] = j;
            const float* base = (m == 0) ? (Wqm1 + j * 384) : (m == 1) ? (Wql1 + j * 384) : (Wh1 + j * 448);
            w4[q] = (const ull2*)base;
        }
        const ull2* x4[4];
        #pragma unroll
        for (int rr = 0; rr < 4; rr++) x4[rr] = (const ull2*)(sx + (rr * 16 + g) * XS);
        u64 acc[5][4];
        #pragma unroll
        for (int q = 0; q < 5; q++)
            #pragma unroll
            for (int rr = 0; rr < 4; rr++) acc[q][rr] = 0;
        #pragma unroll 4
        for (int k = 0; k < I_ / 4; k++) {
            ull2 xv[4];
            #pragma unroll
            for (int rr = 0; rr < 4; rr++) xv[rr] = x4[rr][k];
            #pragma unroll
            for (int q = 0; q < 5; q++) {
                ull2 wv = w4[q][k];
                #pragma unroll
                for (int rr = 0; rr < 4; rr++) {
                    acc[q][rr] = f2fma(wv.x, xv[rr].x, acc[q][rr]);
                    acc[q][rr] = f2fma(wv.y, xv[rr].y, acc[q][rr]);
                }
            }
        }
        #pragma unroll
        for (int q = 0; q < 5; q++) {
            int m = ms[q], j = js[q];
            float* dst = (m == 0) ? g_preQM : (m == 1) ? g_preQL : g_preH;
            float bias = sb[m * 64 + j];
            #pragma unroll
            for (int rr = 0; rr < 4; rr++)
                dst[(bt0 + rr * 16 + g) * P_ + j] = bias + hsum(acc[q][rr]);
        }
    }
}

// ===================== Phase B: sequential recurrence =====================
constexpr int WS = 260;
constexpr int O_W1 = 0, O_W2T = O_W1 + 3 * P_ * WS, O_B2 = O_W2T + 50 * 128;
constexpr int O_BH2 = O_B2 + 128, O_H = O_BH2 + 256, O_A1 = O_H + 4 * WS;
constexpr int O_VH = O_A1 + 200, O_AH = O_VH + 104, O_Z = O_AH + 104;
constexpr size_t SMEM_SEQ = (size_t)(O_Z + 136) * sizeof(float);

__global__ __launch_bounds__(256, 1) void k_seq(
    const float* __restrict__ hidden, const float* __restrict__ noise,
    const float* __restrict__ Wqm1, const float* __restrict__ Wqm2, const float* __restrict__ bqm2,
    const float* __restrict__ Wql1, const float* __restrict__ Wql2, const float* __restrict__ bql2,
    const float* __restrict__ Wh1,  const float* __restrict__ Wh2,  const float* __restrict__ bh2,
    float* __restrict__ out)
{
    extern __shared__ float sm[];
    float* sW1 = sm + O_W1; float* sW2t = sm + O_W2T; float* sb2 = sm + O_B2;
    float* sbh2 = sm + O_BH2; float* sH = sm + O_H; float* sA1 = sm + O_A1;
    float* sVH = sm + O_VH; float* sAH = sm + O_AH; float* sZ = sm + O_Z;

    const int tid = threadIdx.x;
    const int r0 = blockIdx.x * 2;

    for (int idx = tid; idx < P_ * H_; idx += 256) {
        int j = idx >> 8, k = idx & 255;
        sW1[j * WS + k] = Wqm1[j * 384 + 128 + k];
        sW1[(P_ + j) * WS + k] = Wql1[j * 384 + 128 + k];
        sW1[(2 * P_ + j) * WS + k] = Wh1[j * 448 + 128 + k];
    }
    for (int idx = tid; idx < L_ * P_; idx += 256) {
        int n = idx / P_, j = idx - n * P_;
        sW2t[j * 128 + 2 * n] = Wqm2[n * P_ + j];
        sW2t[j * 128 + 2 * n + 1] = Wql2[n * P_ + j];
    }
    if (tid < L_) { sb2[2 * tid] = bqm2[tid]; sb2[2 * tid + 1] = bql2[tid]; }
    if (tid < H_) sbh2[tid] = bh2[tid];
    for (int idx = tid; idx < 2 * H_; idx += 256)
        sH[(idx >> 8) * WS + (idx & 255)] = hidden[(r0 + (idx >> 8)) * H_ + (idx & 255)];
    if (tid == 0) { sAH[50] = sAH[51] = sAH[102] = sAH[103] = 0.f; }

    __half2 wh2c[52];
    {
        int kp = tid & 127;
        #pragma unroll
        for (int j = 0; j < 50; j++)
            wh2c[j] = __floats2half2_rn(Wh2[2 * kp * P_ + j], Wh2[(2 * kp + 1) * P_ + j]);
        wh2c[50] = wh2c[51] = __floats2half2_rn(0.f, 0.f);
    }
    __half2 wzc[32];
    if (tid < 100) {
        int j = tid % 50;
        #pragma unroll
        for (int i = 0; i < 32; i++)
            wzc[i] = __floats2half2_rn(Wh1[j * 448 + 384 + 2 * i], Wh1[j * 448 + 384 + 2 * i + 1]);
    }
    __syncthreads();

    int cb = 0;
    for (int t = 0; t < T_; t++) {
        const long bt0 = (long)r0 * T_ + t, bt1 = bt0 + T_;
        float e = 0.f;
        if (tid < 128) e = noise[((tid >> 6) ? bt1 : bt0) * L_ + (tid & 63)];

        // s1: 150 threads, one (m,j) row each, BOTH batch rows
        if (tid < 150) {
            int m = tid / 50, j = tid - m * 50;
            const ull2* w = (const ull2*)(sW1 + tid * WS);
            const ull2* h0 = (const ull2*)(sH + (cb * 2) * WS);
            const ull2* h1 = (const ull2*)(sH + (cb * 2 + 1) * WS);
            u64 aA0 = 0, aB0 = 0, aA1 = 0, aB1 = 0;
            #pragma unroll 8
            for (int k = 0; k < 64; k++) {
                ull2 wv = w[k], hv0 = h0[k], hv1 = h1[k];
                aA0 = f2fma(wv.x, hv0.x, aA0); aB0 = f2fma(wv.y, hv0.y, aB0);
                aA1 = f2fma(wv.x, hv1.x, aA1); aB1 = f2fma(wv.y, hv1.y, aB1);
            }
            const float* pre = (m == 0) ? g_preQM : (m == 1) ? g_preQL : g_preH;
            float s0 = pre[bt0 * P_ + j] + hsum(aA0) + hsum(aB0);
            float s1v = pre[bt1 * P_ + j] + hsum(aA1) + hsum(aB1);
            if (m == 0)      { sA1[j * 4 + 0] = fmaxf(s0, 0.f); sA1[j * 4 + 2] = fmaxf(s1v, 0.f); }
            else if (m == 1) { sA1[j * 4 + 1] = fmaxf(s0, 0.f); sA1[j * 4 + 3] = fmaxf(s1v, 0.f); }
            else             { sVH[j] = s0; sVH[52 + j] = s1v; }
        } else {
            for (int idx = tid - 150; idx < 2 * H_; idx += 106) {
                int r = idx >> 8, k = idx & 255;
                g_H[(r ? bt1 : bt0) * H_ + k] = sH[(cb * 2 + r) * WS + k];
            }
        }
        __syncthreads();

        // s2: 128 threads (r,n): packed (qmu,qlv) + z
        if (tid < 128) {
            int r = tid >> 6, n = tid & 63;
            long bt = r ? bt1 : bt0;
            u64 acc = pk(sb2[2 * n], sb2[2 * n + 1]);
            const u64* wp = (const u64*)(sW2t + 2 * n);
            const u64* ap = (const u64*)(sA1 + 2 * r);
            #pragma unroll 10
            for (int j = 0; j < 50; j++)
                acc = f2fma(wp[j * 64], ap[j * 2], acc);
            float2 q = up(acc);
            out[QMU_OFF + bt * L_ + n] = q.x;
            out[QLV_OFF + bt * L_ + n] = q.y;
            float z = q.x + __expf(0.5f * q.y) * e;
            sZ[r * 68 + n] = z;
            g_Z[bt * L_ + n] = z;
        }
        __syncthreads();

        // s3: add z-part (reg fp16 Wz), relu
        if (tid < 100) {
            int r = tid / 50, j = tid - r * 50;
            const float4* z4 = (const float4*)(sZ + r * 68);
            u64 acc1 = 0, acc2 = 0;
            #pragma unroll
            for (int i = 0; i < 16; i++) {
                float4 z = z4[i];
                float2 wa = __half22float2(wzc[2 * i]);
                float2 wb = __half22float2(wzc[2 * i + 1]);
                acc1 = f2fma(pk(wa.x, wa.y), pk(z.x, z.y), acc1);
                acc2 = f2fma(pk(wb.x, wb.y), pk(z.z, z.w), acc2);
            }
            sAH[r * 52 + j] = fmaxf(sVH[r * 52 + j] + hsum(acc1) + hsum(acc2), 0.f);
        }
        __syncthreads();

        // s4: h_next = Wh2 @ a + bh2 (reg fp16 Wh2)
        {
            int r = tid >> 7, kp = tid & 127;
            const float4* a4 = (const float4*)(sAH + r * 52);
            float2 bb = *(const float2*)(sbh2 + 2 * kp);
            u64 acc = pk(bb.x, bb.y), acc2 = 0;
            #pragma unroll
            for (int q = 0; q < 13; q++) {
                float4 av = a4[q];
                float2 w0 = __half22float2(wh2c[4 * q]);     acc  = f2fma(pk(w0.x, w0.y), pk(av.x, av.x), acc);
                float2 w1 = __half22float2(wh2c[4 * q + 1]); acc2 = f2fma(pk(w1.x, w1.y), pk(av.y, av.y), acc2);
                float2 w2 = __half22float2(wh2c[4 * q + 2]); acc  = f2fma(pk(w2.x, w2.y), pk(av.z, av.z), acc);
                float2 w3 = __half22float2(wh2c[4 * q + 3]); acc2 = f2fma(pk(w3.x, w3.y), pk(av.w, av.w), acc2);
            }
            float2 r1 = up(acc), r2 = up(acc2);
            int nb = cb ^ 1;
            *(float2*)(sH + (nb * 2 + r) * WS + 2 * kp) = make_float2(r1.x + r2.x, r1.y + r2.y);
        }
        __syncthreads();
        cb ^= 1;
    }
}

// ===================== Phase C1: p-branch MLPs (W1 from gmem) =====================
constexpr int ROWS_P = 32;
constexpr int PO_W2 = 0, PO_B1 = PO_W2 + 2 * L_ * P_, PO_B2 = PO_B1 + 128;
constexpr int PO_H = PO_B2 + 128, PO_A = PO_H + ROWS_P * WS;
constexpr size_t SMEM_P = (size_t)(PO_A + 2 * ROWS_P * 52) * sizeof(float);

__global__ __launch_bounds__(256) void k_pbranch(
    const float* __restrict__ Wpm1, const float* __restrict__ bpm1,
    const float* __restrict__ Wpm2, const float* __restrict__ bpm2,
    const float* __restrict__ Wpl1, const float* __restrict__ bpl1,
    const float* __restrict__ Wpl2, const float* __restrict__ bpl2,
    float* __restrict__ out)
{
    extern __shared__ float sm[];
    float* sW2 = sm + PO_W2; float* sb1 = sm + PO_B1;
    float* sb2 = sm + PO_B2; float* sh = sm + PO_H; float* sa = sm + PO_A;
    const int tid = threadIdx.x;
    const long bt0 = (long)blockIdx.x * ROWS_P;

    for (int idx = tid; idx < L_ * P_; idx += 256) {
        sW2[idx] = Wpm2[idx]; sW2[L_ * P_ + idx] = Wpl2[idx];
    }
    if (tid < P_) { sb1[tid] = bpm1[tid]; sb1[64 + tid] = bpl1[tid]; }
    if (tid < L_) { sb2[tid] = bpm2[tid]; sb2[64 + tid] = bpl2[tid]; }
    for (int idx = tid; idx < ROWS_P * H_; idx += 256)
        sh[(idx >> 8) * WS + (idx & 255)] = g_H[bt0 * H_ + idx];
    __syncthreads();

    if (tid < 100) {
        int op = tid >> 2, g = tid & 3;
        const ull2* w4[4]; const ull2* h4[8];
        #pragma unroll
        for (int q = 0; q < 4; q++) {
            int o = op * 4 + q, m = o / P_, j = o - m * P_;
            w4[q] = (const ull2*)((m == 0 ? Wpm1 : Wpl1) + j * H_);
        }
        #pragma unroll
        for (int rr = 0; rr < 8; rr++) h4[rr] = (const ull2*)(sh + (rr * 4 + g) * WS);
        u64 acc[4][8];
        #pragma unroll
        for (int q = 0; q < 4; q++)
            #pragma unroll
            for (int rr = 0; rr < 8; rr++) acc[q][rr] = 0;
        #pragma unroll 4
        for (int k = 0; k < H_ / 4; k++) {
            ull2 hv[8];
            #pragma unroll
            for (int rr = 0; rr < 8; rr++) hv[rr] = h4[rr][k];
            #pragma unroll
            for (int q = 0; q < 4; q++) {
                ull2 wv = w4[q][k];
                #pragma unroll
                for (int rr = 0; rr < 8; rr++) {
                    acc[q][rr] = f2fma(wv.x, hv[rr].x, acc[q][rr]);
                    acc[q][rr] = f2fma(wv.y, hv[rr].y, acc[q][rr]);
                }
            }
        }
        #pragma unroll
        for (int q = 0; q < 4; q++) {
            int o = op * 4 + q, m = o / P_, j = o - m * P_;
            float bias = sb1[m * 64 + j];
            #pragma unroll
            for (int rr = 0; rr < 8; rr++)
                sa[(m * ROWS_P + rr * 4 + g) * 52 + j] = fmaxf(bias + hsum(acc[q][rr]), 0.f);
        }
    }
    __syncthreads();

    for (int task = tid; task < 2 * ROWS_P * L_; task += 256) {
        int m = task / (ROWS_P * L_); int rn = task - m * ROWS_P * L_;
        int r = rn >> 6, n = rn & 63;
        const float* w = sW2 + (m * L_ + n) * P_;
        const float* a = sa + (m * ROWS_P + r) * 52;
        float acc = sb2[m * 64 + n];
        #pragma unroll
        for (int j = 0; j < P_; j++) acc += w[j] * a[j];
        out[((m == 0) ? PMU_OFF : PLV_OFF) + (bt0 + r) * L_ + n] = acc;
    }
}

// ===================== Phase C2: x_hat (Wo from gmem) =====================
constexpr int ROWS_O = 32;
constexpr int OO_H = 0, OO_Z = OO_H + ROWS_O * WS, OO_B = OO_Z + ROWS_O * 68;
constexpr size_t SMEM_O = (size_t)(OO_B + 128) * sizeof(float);

__global__ __launch_bounds__(128) void k_out(
    const float* __restrict__ Wo, const float* __restrict__ bo, float* __restrict__ out)
{
    extern __shared__ float sm[];
    float* sh = sm + OO_H; float* sz = sm + OO_Z; float* sbo = sm + OO_B;
    const int tid = threadIdx.x;
    const long bt0 = (long)blockIdx.x * ROWS_O;

    for (int idx = tid; idx < ROWS_O * H_; idx += 128)
        sh[(idx >> 8) * WS + (idx & 255)] = g_H[bt0 * H_ + idx];
    for (int idx = tid; idx < ROWS_O * L_; idx += 128)
        sz[(idx >> 6) * 68 + (idx & 63)] = g_Z[bt0 * L_ + idx];
    if (tid < I_) sbo[tid] = bo[tid];
    __syncthreads();

    {
        int ig = tid >> 2, g = tid & 3;
        const ull2* w4[4]; const ull2* h4[8]; const ull2* z4[8];
        #pragma unroll
        for (int q = 0; q < 4; q++) w4[q] = (const ull2*)(Wo + (ig * 4 + q) * 320);
        #pragma unroll
        for (int rr = 0; rr < 8; rr++) {
            h4[rr] = (const ull2*)(sh + (rr * 4 + g) * WS);
            z4[rr] = (const ull2*)(sz + (rr * 4 + g) * 68);
        }
        u64 acc[4][8];
        #pragma unroll
        for (int q = 0; q < 4; q++)
            #pragma unroll
            for (int rr = 0; rr < 8; rr++) acc[q][rr] = 0;
        #pragma unroll 4
        for (int k = 0; k < H_ / 4; k++) {
            ull2 hv[8];
            #pragma unroll
            for (int rr = 0; rr < 8; rr++) hv[rr] = h4[rr][k];
            #pragma unroll
            for (int q = 0; q < 4; q++) {
                ull2 wv = w4[q][k];
                #pragma unroll
                for (int rr = 0; rr < 8; rr++) {
                    acc[q][rr] = f2fma(wv.x, hv[rr].x, acc[q][rr]);
                    acc[q][rr] = f2fma(wv.y, hv[rr].y, acc[q][rr]);
                }
            }
        }
        #pragma unroll
        for (int k = 0; k < L_ / 4; k++) {
            ull2 zv[8];
            #pragma unroll
            for (int rr = 0; rr < 8; rr++) zv[rr] = z4[rr][k];
            #pragma unroll
            for (int q = 0; q < 4; q++) {
                ull2 wv = w4[q][64 + k];
                #pragma unroll
                for (int rr = 0; rr < 8; rr++) {
                    acc[q][rr] = f2fma(wv.x, zv[rr].x, acc[q][rr]);
                    acc[q][rr] = f2fma(wv.y, zv[rr].y, acc[q][rr]);
                }
            }
        }
        #pragma unroll
        for (int q = 0; q < 4; q++) {
            int i = ig * 4 + q; float bias = sbo[i];
            #pragma unroll
            for (int rr = 0; rr < 8; rr++) {
                float v = bias + hsum(acc[q][rr]);
                out[(bt0 + rr * 4 + g) * I_ + i] = 1.0f / (1.0f + __expf(-v));
            }
        }
    }
}

// ===================== launch =====================
extern "C" void kernel_launch(void* const* d_in, const int* in_sizes, int n_in,
                              void* d_out, int out_size) {
    const float* x = (const float*)d_in[0];
    const float* hidden = (const float*)d_in[1];
    const float* noise = (const float*)d_in[2];
    const float* Wpm1 = (const float*)d_in[3];  const float* bpm1 = (const float*)d_in[4];
    const float* Wpm2 = (const float*)d_in[5];  const float* bpm2 = (const float*)d_in[6];
    const float* Wpl1 = (const float*)d_in[7];  const float* bpl1 = (const float*)d_in[8];
    const float* Wpl2 = (const float*)d_in[9];  const float* bpl2 = (const float*)d_in[10];
    const float* Wqm1 = (const float*)d_in[11]; const float* bqm1 = (const float*)d_in[12];
    const float* Wqm2 = (const float*)d_in[13]; const float* bqm2 = (const float*)d_in[14];
    const float* Wql1 = (const float*)d_in[15]; const float* bql1 = (const float*)d_in[16];
    const float* Wql2 = (const float*)d_in[17]; const float* bql2 = (const float*)d_in[18];
    const float* Wh1 = (const float*)d_in[19];  const float* bh1 = (const float*)d_in[20];
    const float* Wh2 = (const float*)d_in[21];  const float* bh2 = (const float*)d_in[22];
    const float* Wo = (const float*)d_in[23];   const float* bo = (const float*)d_in[24];
    float* out = (float*)d_out;

    cudaFuncSetAttribute(k_pre, cudaFuncAttributeMaxDynamicSharedMemorySize, (int)SMEM_PRE);
    cudaFuncSetAttribute(k_seq, cudaFuncAttributeMaxDynamicSharedMemorySize, (int)SMEM_SEQ);
    cudaFuncSetAttribute(k_pbranch, cudaFuncAttributeMaxDynamicSharedMemorySize, (int)SMEM_P);
    cudaFuncSetAttribute(k_out, cudaFuncAttributeMaxDynamicSharedMemorySize, (int)SMEM_O);

    k_pre<<<(int)(BT / ROWS_A), 256, SMEM_PRE>>>(x, Wqm1, bqm1, Wql1, bql1, Wh1, bh1);
    k_seq<<<B_ / 2, 256, SMEM_SEQ>>>(hidden, noise, Wqm1, Wqm2, bqm2,
                                     Wql1, Wql2, bql2, Wh1, Wh2, bh2, out);
    k_pbranch<<<(int)(BT / ROWS_P), 256, SMEM_P>>>(Wpm1, bpm1, Wpm2, bpm2,
                                                   Wpl1, bpl1, Wpl2, bpl2, out);
    k_out<<<(int)(BT / ROWS_O), 128, SMEM_O>>>(Wo, bo, out);
}

// round 14
// speedup vs baseline: 1.6371x; 1.0444x over previous
#include <cuda_runtime.h>
#include <cuda_fp16.h>
#include <math.h>

constexpr int  B_ = 256, T_ = 512, I_ = 128, H_ = 256, L_ = 64, P_ = 50;
constexpr long BT = (long)B_ * T_;
constexpr long PMU_OFF = BT * I_, PLV_OFF = PMU_OFF + BT * L_;
constexpr long QMU_OFF = PLV_OFF + BT * L_, QLV_OFF = QMU_OFF + BT * L_;
constexpr int CHUNK = 128, NCHUNK = T_ / CHUNK;

__device__ float g_H[BT * H_];
__device__ float g_Z[BT * L_];
__device__ float g_preQM[BT * P_];
__device__ float g_preQL[BT * P_];
__device__ float g_preH[BT * P_];

using u64 = unsigned long long;
__device__ __forceinline__ u64 pk(float x, float y) {
    u64 r; asm("mov.b64 %0,{%1,%2};" : "=l"(r) : "f"(x), "f"(y)); return r;
}
__device__ __forceinline__ float2 up(u64 v) {
    float2 f; asm("mov.b64 {%0,%1},%2;" : "=f"(f.x), "=f"(f.y) : "l"(v)); return f;
}
__device__ __forceinline__ u64 f2fma(u64 a, u64 b, u64 c) {
    u64 d; asm("fma.rn.f32x2 %0,%1,%2,%3;" : "=l"(d) : "l"(a), "l"(b), "l"(c)); return d;
}
__device__ __forceinline__ float hsum(u64 v) { float2 f = up(v); return f.x + f.y; }
using ull2 = ulonglong2;

// ===================== Phase A =====================
constexpr int ROWS_A = 64, XS = 132;
constexpr size_t SMEM_PRE = (size_t)(ROWS_A * XS + 192) * sizeof(float);

__global__ __launch_bounds__(256) void k_pre(
    const float* __restrict__ x,
    const float* __restrict__ Wqm1, const float* __restrict__ bqm1,
    const float* __restrict__ Wql1, const float* __restrict__ bql1,
    const float* __restrict__ Wh1,  const float* __restrict__ bh1)
{
    extern __shared__ float sm[];
    float* sx = sm; float* sb = sx + ROWS_A * XS;
    const int tid = threadIdx.x;
    const long bt0 = (long)blockIdx.x * ROWS_A;

    for (int idx = tid; idx < ROWS_A * I_; idx += 256)
        sx[(idx >> 7) * XS + (idx & 127)] = x[bt0 * I_ + idx];
    if (tid < P_) { sb[tid] = bqm1[tid]; sb[64 + tid] = bql1[tid]; sb[128 + tid] = bh1[tid]; }
    __syncthreads();

    for (int task = tid; task < 480; task += 256) {
        int og = task >> 4, g = task & 15;
        const ull2* w4[5]; int ms[5], js[5];
        #pragma unroll
        for (int q = 0; q < 5; q++) {
            int o = og * 5 + q, m = o / P_, j = o - m * P_;
            ms[q] = m; js[q] = j;
            const float* base = (m == 0) ? (Wqm1 + j * 384) : (m == 1) ? (Wql1 + j * 384) : (Wh1 + j * 448);
            w4[q] = (const ull2*)base;
        }
        const ull2* x4[4];
        #pragma unroll
        for (int rr = 0; rr < 4; rr++) x4[rr] = (const ull2*)(sx + (rr * 16 + g) * XS);
        u64 acc[5][4];
        #pragma unroll
        for (int q = 0; q < 5; q++)
            #pragma unroll
            for (int rr = 0; rr < 4; rr++) acc[q][rr] = 0;
        #pragma unroll 4
        for (int k = 0; k < I_ / 4; k++) {
            ull2 xv[4];
            #pragma unroll
            for (int rr = 0; rr < 4; rr++) xv[rr] = x4[rr][k];
            #pragma unroll
            for (int q = 0; q < 5; q++) {
                ull2 wv = w4[q][k];
                #pragma unroll
                for (int rr = 0; rr < 4; rr++) {
                    acc[q][rr] = f2fma(wv.x, xv[rr].x, acc[q][rr]);
                    acc[q][rr] = f2fma(wv.y, xv[rr].y, acc[q][rr]);
                }
            }
        }
        #pragma unroll
        for (int q = 0; q < 5; q++) {
            int m = ms[q], j = js[q];
            float* dst = (m == 0) ? g_preQM : (m == 1) ? g_preQL : g_preH;
            float bias = sb[m * 64 + j];
            #pragma unroll
            for (int rr = 0; rr < 4; rr++)
                dst[(bt0 + rr * 16 + g) * P_ + j] = bias + hsum(acc[q][rr]);
        }
    }
}

// ===================== Phase B (chunked) =====================
constexpr int WS = 260;
constexpr int O_W1 = 0, O_W2T = O_W1 + 3 * P_ * WS, O_B2 = O_W2T + 50 * 128;
constexpr int O_BH2 = O_B2 + 128, O_H = O_BH2 + 256, O_A1 = O_H + 4 * WS;
constexpr int O_VH = O_A1 + 200, O_AH = O_VH + 104, O_Z = O_AH + 104;
constexpr size_t SMEM_SEQ = (size_t)(O_Z + 136) * sizeof(float);

__global__ __launch_bounds__(256, 1) void k_seq(
    const float* __restrict__ hidden, const float* __restrict__ noise,
    const float* __restrict__ Wqm1, const float* __restrict__ Wqm2, const float* __restrict__ bqm2,
    const float* __restrict__ Wql1, const float* __restrict__ Wql2, const float* __restrict__ bql2,
    const float* __restrict__ Wh1,  const float* __restrict__ Wh2,  const float* __restrict__ bh2,
    float* __restrict__ out, int t0, int t1)
{
    extern __shared__ float sm[];
    float* sW1 = sm + O_W1; float* sW2t = sm + O_W2T; float* sb2 = sm + O_B2;
    float* sbh2 = sm + O_BH2; float* sH = sm + O_H; float* sA1 = sm + O_A1;
    float* sVH = sm + O_VH; float* sAH = sm + O_AH; float* sZ = sm + O_Z;

    const int tid = threadIdx.x;
    const int r0 = blockIdx.x * 2;

    for (int idx = tid; idx < P_ * H_; idx += 256) {
        int j = idx >> 8, k = idx & 255;
        sW1[j * WS + k] = Wqm1[j * 384 + 128 + k];
        sW1[(P_ + j) * WS + k] = Wql1[j * 384 + 128 + k];
        sW1[(2 * P_ + j) * WS + k] = Wh1[j * 448 + 128 + k];
    }
    for (int idx = tid; idx < L_ * P_; idx += 256) {
        int n = idx / P_, j = idx - n * P_;
        sW2t[j * 128 + 2 * n] = Wqm2[n * P_ + j];
        sW2t[j * 128 + 2 * n + 1] = Wql2[n * P_ + j];
    }
    if (tid < L_) { sb2[2 * tid] = bqm2[tid]; sb2[2 * tid + 1] = bql2[tid]; }
    if (tid < H_) sbh2[tid] = bh2[tid];
    for (int idx = tid; idx < 2 * H_; idx += 256) {
        int r = idx >> 8, k = idx & 255;
        sH[r * WS + k] = (t0 == 0) ? hidden[(r0 + r) * H_ + k]
                                   : g_H[((long)(r0 + r) * T_ + t0) * H_ + k];
    }
    if (tid == 0) { sAH[50] = sAH[51] = sAH[102] = sAH[103] = 0.f; }

    __half2 wh2c[52];
    {
        int kp = tid & 127;
        #pragma unroll
        for (int j = 0; j < 50; j++)
            wh2c[j] = __floats2half2_rn(Wh2[2 * kp * P_ + j], Wh2[(2 * kp + 1) * P_ + j]);
        wh2c[50] = wh2c[51] = __floats2half2_rn(0.f, 0.f);
    }
    __half2 wzc[32];
    if (tid < 100) {
        int j = tid % 50;
        #pragma unroll
        for (int i = 0; i < 32; i++)
            wzc[i] = __floats2half2_rn(Wh1[j * 448 + 384 + 2 * i], Wh1[j * 448 + 384 + 2 * i + 1]);
    }
    __syncthreads();

    int cb = 0;
    for (int t = t0; t < t1; t++) {
        const long bt0v = (long)r0 * T_ + t, bt1v = bt0v + T_;
        float e = 0.f;
        if (tid < 128) e = noise[((tid >> 6) ? bt1v : bt0v) * L_ + (tid & 63)];

        if (tid < 150) {
            int m = tid / 50, j = tid - m * 50;
            const ull2* w = (const ull2*)(sW1 + tid * WS);
            const ull2* h0 = (const ull2*)(sH + (cb * 2) * WS);
            const ull2* h1 = (const ull2*)(sH + (cb * 2 + 1) * WS);
            u64 aA0 = 0, aB0 = 0, aA1 = 0, aB1 = 0;
            #pragma unroll 8
            for (int k = 0; k < 64; k++) {
                ull2 wv = w[k], hv0 = h0[k], hv1 = h1[k];
                aA0 = f2fma(wv.x, hv0.x, aA0); aB0 = f2fma(wv.y, hv0.y, aB0);
                aA1 = f2fma(wv.x, hv1.x, aA1); aB1 = f2fma(wv.y, hv1.y, aB1);
            }
            const float* pre = (m == 0) ? g_preQM : (m == 1) ? g_preQL : g_preH;
            float s0 = pre[bt0v * P_ + j] + hsum(aA0) + hsum(aB0);
            float s1v = pre[bt1v * P_ + j] + hsum(aA1) + hsum(aB1);
            if (m == 0)      { sA1[j * 4 + 0] = fmaxf(s0, 0.f); sA1[j * 4 + 2] = fmaxf(s1v, 0.f); }
            else if (m == 1) { sA1[j * 4 + 1] = fmaxf(s0, 0.f); sA1[j * 4 + 3] = fmaxf(s1v, 0.f); }
            else             { sVH[j] = s0; sVH[52 + j] = s1v; }
        } else {
            for (int idx = tid - 150; idx < 2 * H_; idx += 106) {
                int r = idx >> 8, k = idx & 255;
                g_H[(r ? bt1v : bt0v) * H_ + k] = sH[(cb * 2 + r) * WS + k];
            }
        }
        __syncthreads();

        if (tid < 128) {
            int r = tid >> 6, n = tid & 63;
            long bt = r ? bt1v : bt0v;
            u64 acc = pk(sb2[2 * n], sb2[2 * n + 1]);
            const u64* wp = (const u64*)(sW2t + 2 * n);
            const u64* ap = (const u64*)(sA1 + 2 * r);
            #pragma unroll 10
            for (int j = 0; j < 50; j++)
                acc = f2fma(wp[j * 64], ap[j * 2], acc);
            float2 q = up(acc);
            out[QMU_OFF + bt * L_ + n] = q.x;
            out[QLV_OFF + bt * L_ + n] = q.y;
            float z = q.x + __expf(0.5f * q.y) * e;
            sZ[r * 68 + n] = z;
            g_Z[bt * L_ + n] = z;
        }
        __syncthreads();

        if (tid < 100) {
            int r = tid / 50, j = tid - r * 50;
            const float4* z4 = (const float4*)(sZ + r * 68);
            u64 acc1 = 0, acc2 = 0;
            #pragma unroll
            for (int i = 0; i < 16; i++) {
                float4 z = z4[i];
                float2 wa = __half22float2(wzc[2 * i]);
                float2 wb = __half22float2(wzc[2 * i + 1]);
                acc1 = f2fma(pk(wa.x, wa.y), pk(z.x, z.y), acc1);
                acc2 = f2fma(pk(wb.x, wb.y), pk(z.z, z.w), acc2);
            }
            sAH[r * 52 + j] = fmaxf(sVH[r * 52 + j] + hsum(acc1) + hsum(acc2), 0.f);
        }
        __syncthreads();

        {
            int r = tid >> 7, kp = tid & 127;
            const float4* a4 = (const float4*)(sAH + r * 52);
            float2 bb = *(const float2*)(sbh2 + 2 * kp);
            u64 acc = pk(bb.x, bb.y), acc2 = 0;
            #pragma unroll
            for (int q = 0; q < 13; q++) {
                float4 av = a4[q];
                float2 w0 = __half22float2(wh2c[4 * q]);     acc  = f2fma(pk(w0.x, w0.y), pk(av.x, av.x), acc);
                float2 w1 = __half22float2(wh2c[4 * q + 1]); acc2 = f2fma(pk(w1.x, w1.y), pk(av.y, av.y), acc2);
                float2 w2 = __half22float2(wh2c[4 * q + 2]); acc  = f2fma(pk(w2.x, w2.y), pk(av.z, av.z), acc);
                float2 w3 = __half22float2(wh2c[4 * q + 3]); acc2 = f2fma(pk(w3.x, w3.y), pk(av.w, av.w), acc2);
            }
            float2 r1 = up(acc), r2 = up(acc2);
            int nb = cb ^ 1;
            *(float2*)(sH + (nb * 2 + r) * WS + 2 * kp) = make_float2(r1.x + r2.x, r1.y + r2.y);
        }
        __syncthreads();
        cb ^= 1;
    }

    // hand off h to next chunk
    if (t1 < T_) {
        for (int idx = tid; idx < 2 * H_; idx += 256) {
            int r = idx >> 8, k = idx & 255;
            g_H[((long)(r0 + r) * T_ + t1) * H_ + k] = sH[(cb * 2 + r) * WS + k];
        }
    }
}

// ===================== Phase C1 (chunked) =====================
constexpr int ROWS_P = 32;
constexpr int PO_W2 = 0, PO_B1 = PO_W2 + 2 * L_ * P_, PO_B2 = PO_B1 + 128;
constexpr int PO_H = PO_B2 + 128, PO_A = PO_H + ROWS_P * WS;
constexpr size_t SMEM_P = (size_t)(PO_A + 2 * ROWS_P * 52) * sizeof(float);

__global__ __launch_bounds__(256) void k_pbranch(
    const float* __restrict__ Wpm1, const float* __restrict__ bpm1,
    const float* __restrict__ Wpm2, const float* __restrict__ bpm2,
    const float* __restrict__ Wpl1, const float* __restrict__ bpl1,
    const float* __restrict__ Wpl2, const float* __restrict__ bpl2,
    float* __restrict__ out, int t0)
{
    extern __shared__ float sm[];
    float* sW2 = sm + PO_W2; float* sb1 = sm + PO_B1;
    float* sb2 = sm + PO_B2; float* sh = sm + PO_H; float* sa = sm + PO_A;
    const int tid = threadIdx.x;
    const int b = blockIdx.x >> 2, seg = blockIdx.x & 3;
    const long bt0 = (long)b * T_ + t0 + seg * ROWS_P;

    for (int idx = tid; idx < L_ * P_; idx += 256) {
        sW2[idx] = Wpm2[idx]; sW2[L_ * P_ + idx] = Wpl2[idx];
    }
    if (tid < P_) { sb1[tid] = bpm1[tid]; sb1[64 + tid] = bpl1[tid]; }
    if (tid < L_) { sb2[tid] = bpm2[tid]; sb2[64 + tid] = bpl2[tid]; }
    for (int idx = tid; idx < ROWS_P * H_; idx += 256)
        sh[(idx >> 8) * WS + (idx & 255)] = g_H[bt0 * H_ + idx];
    __syncthreads();

    if (tid < 100) {
        int op = tid >> 2, g = tid & 3;
        const ull2* w4[4]; const ull2* h4[8];
        #pragma unroll
        for (int q = 0; q < 4; q++) {
            int o = op * 4 + q, m = o / P_, j = o - m * P_;
            w4[q] = (const ull2*)((m == 0 ? Wpm1 : Wpl1) + j * H_);
        }
        #pragma unroll
        for (int rr = 0; rr < 8; rr++) h4[rr] = (const ull2*)(sh + (rr * 4 + g) * WS);
        u64 acc[4][8];
        #pragma unroll
        for (int q = 0; q < 4; q++)
            #pragma unroll
            for (int rr = 0; rr < 8; rr++) acc[q][rr] = 0;
        #pragma unroll 4
        for (int k = 0; k < H_ / 4; k++) {
            ull2 hv[8];
            #pragma unroll
            for (int rr = 0; rr < 8; rr++) hv[rr] = h4[rr][k];
            #pragma unroll
            for (int q = 0; q < 4; q++) {
                ull2 wv = w4[q][k];
                #pragma unroll
                for (int rr = 0; rr < 8; rr++) {
                    acc[q][rr] = f2fma(wv.x, hv[rr].x, acc[q][rr]);
                    acc[q][rr] = f2fma(wv.y, hv[rr].y, acc[q][rr]);
                }
            }
        }
        #pragma unroll
        for (int q = 0; q < 4; q++) {
            int o = op * 4 + q, m = o / P_, j = o - m * P_;
            float bias = sb1[m * 64 + j];
            #pragma unroll
            for (int rr = 0; rr < 8; rr++)
                sa[(m * ROWS_P + rr * 4 + g) * 52 + j] = fmaxf(bias + hsum(acc[q][rr]), 0.f);
        }
    }
    __syncthreads();

    for (int task = tid; task < 2 * ROWS_P * L_; task += 256) {
        int m = task / (ROWS_P * L_); int rn = task - m * ROWS_P * L_;
        int r = rn >> 6, n = rn & 63;
        const float* w = sW2 + (m * L_ + n) * P_;
        const float* a = sa + (m * ROWS_P + r) * 52;
        float acc = sb2[m * 64 + n];
        #pragma unroll
        for (int j = 0; j < P_; j++) acc += w[j] * a[j];
        out[((m == 0) ? PMU_OFF : PLV_OFF) + (bt0 + r) * L_ + n] = acc;
    }
}

// ===================== Phase C2 (chunked) =====================
constexpr int ROWS_O = 32;
constexpr int OO_H = 0, OO_Z = OO_H + ROWS_O * WS, OO_B = OO_Z + ROWS_O * 68;
constexpr size_t SMEM_O = (size_t)(OO_B + 128) * sizeof(float);

__global__ __launch_bounds__(128) void k_out(
    const float* __restrict__ Wo, const float* __restrict__ bo, float* __restrict__ out, int t0)
{
    extern __shared__ float sm[];
    float* sh = sm + OO_H; float* sz = sm + OO_Z; float* sbo = sm + OO_B;
    const int tid = threadIdx.x;
    const int b = blockIdx.x >> 2, seg = blockIdx.x & 3;
    const long bt0 = (long)b * T_ + t0 + seg * ROWS_O;

    for (int idx = tid; idx < ROWS_O * H_; idx += 128)
        sh[(idx >> 8) * WS + (idx & 255)] = g_H[bt0 * H_ + idx];
    for (int idx = tid; idx < ROWS_O * L_; idx += 128)
        sz[(idx >> 6) * 68 + (idx & 63)] = g_Z[bt0 * L_ + idx];
    if (tid < I_) sbo[tid] = bo[tid];
    __syncthreads();

    {
        int ig = tid >> 2, g = tid & 3;
        const ull2* w4[4]; const ull2* h4[8]; const ull2* z4[8];
        #pragma unroll
        for (int q = 0; q < 4; q++) w4[q] = (const ull2*)(Wo + (ig * 4 + q) * 320);
        #pragma unroll
        for (int rr = 0; rr < 8; rr++) {
            h4[rr] = (const ull2*)(sh + (rr * 4 + g) * WS);
            z4[rr] = (const ull2*)(sz + (rr * 4 + g) * 68);
        }
        u64 acc[4][8];
        #pragma unroll
        for (int q = 0; q < 4; q++)
            #pragma unroll
            for (int rr = 0; rr < 8; rr++) acc[q][rr] = 0;
        #pragma unroll 4
        for (int k = 0; k < H_ / 4; k++) {
            ull2 hv[8];
            #pragma unroll
            for (int rr = 0; rr < 8; rr++) hv[rr] = h4[rr][k];
            #pragma unroll
            for (int q = 0; q < 4; q++) {
                ull2 wv = w4[q][k];
                #pragma unroll
                for (int rr = 0; rr < 8; rr++) {
                    acc[q][rr] = f2fma(wv.x, hv[rr].x, acc[q][rr]);
                    acc[q][rr] = f2fma(wv.y, hv[rr].y, acc[q][rr]);
                }
            }
        }
        #pragma unroll
        for (int k = 0; k < L_ / 4; k++) {
            ull2 zv[8];
            #pragma unroll
            for (int rr = 0; rr < 8; rr++) zv[rr] = z4[rr][k];
            #pragma unroll
            for (int q = 0; q < 4; q++) {
                ull2 wv = w4[q][64 + k];
                #pragma unroll
                for (int rr = 0; rr < 8; rr++) {
                    acc[q][rr] = f2fma(wv.x, zv[rr].x, acc[q][rr]);
                    acc[q][rr] = f2fma(wv.y, zv[rr].y, acc[q][rr]);
                }
            }
        }
        #pragma unroll
        for (int q = 0; q < 4; q++) {
            int i = ig * 4 + q; float bias = sbo[i];
            #pragma unroll
            for (int rr = 0; rr < 8; rr++) {
                float v = bias + hsum(acc[q][rr]);
                out[(bt0 + rr * 4 + g) * I_ + i] = 1.0f / (1.0f + __expf(-v));
            }
        }
    }
}

// ===================== launch: pipelined chunks =====================
extern "C" void kernel_launch(void* const* d_in, const int* in_sizes, int n_in,
                              void* d_out, int out_size) {
    const float* x = (const float*)d_in[0];
    const float* hidden = (const float*)d_in[1];
    const float* noise = (const float*)d_in[2];
    const float* Wpm1 = (const float*)d_in[3];  const float* bpm1 = (const float*)d_in[4];
    const float* Wpm2 = (const float*)d_in[5];  const float* bpm2 = (const float*)d_in[6];
    const float* Wpl1 = (const float*)d_in[7];  const float* bpl1 = (const float*)d_in[8];
    const float* Wpl2 = (const float*)d_in[9];  const float* bpl2 = (const float*)d_in[10];
    const float* Wqm1 = (const float*)d_in[11]; const float* bqm1 = (const float*)d_in[12];
    const float* Wqm2 = (const float*)d_in[13]; const float* bqm2 = (const float*)d_in[14];
    const float* Wql1 = (const float*)d_in[15]; const float* bql1 = (const float*)d_in[16];
    const float* Wql2 = (const float*)d_in[17]; const float* bql2 = (const float*)d_in[18];
    const float* Wh1 = (const float*)d_in[19];  const float* bh1 = (const float*)d_in[20];
    const float* Wh2 = (const float*)d_in[21];  const float* bh2 = (const float*)d_in[22];
    const float* Wo = (const float*)d_in[23];   const float* bo = (const float*)d_in[24];
    float* out = (float*)d_out;

    cudaFuncSetAttribute(k_pre, cudaFuncAttributeMaxDynamicSharedMemorySize, (int)SMEM_PRE);
    cudaFuncSetAttribute(k_seq, cudaFuncAttributeMaxDynamicSharedMemorySize, (int)SMEM_SEQ);
    cudaFuncSetAttribute(k_pbranch, cudaFuncAttributeMaxDynamicSharedMemorySize, (int)SMEM_P);
    cudaFuncSetAttribute(k_out, cudaFuncAttributeMaxDynamicSharedMemorySize, (int)SMEM_O);

    cudaStream_t s1;
    cudaStreamCreateWithFlags(&s1, cudaStreamNonBlocking);
    cudaEvent_t evA[NCHUNK], evB;
    for (int c = 0; c < NCHUNK; c++) cudaEventCreateWithFlags(&evA[c], cudaEventDisableTiming);
    cudaEventCreateWithFlags(&evB, cudaEventDisableTiming);

    k_pre<<<(int)(BT / ROWS_A), 256, SMEM_PRE>>>(x, Wqm1, bqm1, Wql1, bql1, Wh1, bh1);

    const int gridC = B_ * (CHUNK / ROWS_P);  // 1024
    for (int c = 0; c < NCHUNK; c++) {
        int t0 = c * CHUNK, t1 = t0 + CHUNK;
        k_seq<<<B_ / 2, 256, SMEM_SEQ>>>(hidden, noise, Wqm1, Wqm2, bqm2,
                                         Wql1, Wql2, bql2, Wh1, Wh2, bh2, out, t0, t1);
        cudaEventRecord(evA[c], 0);
        cudaStreamWaitEvent(s1, evA[c], 0);
        k_pbranch<<<gridC, 256, SMEM_P, s1>>>(Wpm1, bpm1, Wpm2, bpm2,
                                              Wpl1, bpl1, Wpl2, bpl2, out, t0);
        k_out<<<gridC, 128, SMEM_O, s1>>>(Wo, bo, out, t0);
    }
    cudaEventRecord(evB, s1);
    cudaStreamWaitEvent(0, evB, 0);
}